// round 8
// baseline (speedup 1.0000x reference)
#include <cuda_runtime.h>
#include <cuda_bf16.h>
#include <math.h>
#include <stdint.h>

// Problem constants
#define NB     64
#define DIM    64
#define HW     1024
#define NTOK   65536         // NB*HW
#define KCODES 1024
#define ZQ_ELEMS 4194304     // NB*DIM*HW
#define CHUNK  64            // codes per smem chunk
#define NCHUNKS (KCODES / CHUNK)   // 16
#define EPS    0.12f

// ---------------------------------------------------------------------------
// Device global scratch (no allocation allowed)
// tf32 fragment-ordered codebook: [chunk][n8][ks(8)][lane] -> float2
//   lane = g*4 + t4 ; code = chunk*64 + n8*8 + g
//   .x = tf32(c[code][ks*8 + t4]), .y = tf32(c[code][ks*8 + t4 + 4])
// ---------------------------------------------------------------------------
__device__ __align__(16) float2 g_cbf[NCHUNKS * 8 * 8 * 32];   // 256 KB
__device__ float g_cnorm[KCODES];
__device__ int   g_idx[NTOK];
__device__ int   g_rescue[NTOK];
__device__ int   g_rescue_cnt;
__device__ float g_losssum;
__device__ int   g_hist[KCODES];

// ---------------------------------------------------------------------------
// Helpers
// ---------------------------------------------------------------------------
__device__ __forceinline__ float to_tf32(float v) {
    float o;
    asm("cvt.rna.tf32.f32 %0, %1;" : "=f"(o) : "f"(v));
    return o;
}
__device__ __forceinline__ void mma1688_tf32(float* c, const float* a,
                                             float b0, float b1) {
    asm volatile(
        "mma.sync.aligned.m16n8k8.row.col.f32.tf32.tf32.f32 "
        "{%0,%1,%2,%3}, {%4,%5,%6,%7}, {%8,%9}, {%0,%1,%2,%3};"
        : "+f"(c[0]), "+f"(c[1]), "+f"(c[2]), "+f"(c[3])
        : "f"(a[0]), "f"(a[1]), "f"(a[2]), "f"(a[3]), "f"(b0), "f"(b1));
}
__device__ __forceinline__ uint32_t smem_u32(const void* p) {
    uint32_t a;
    asm("{ .reg .u64 t; cvta.to.shared.u64 t, %1; cvt.u32.u64 %0, t; }"
        : "=r"(a) : "l"(p));
    return a;
}
__device__ __forceinline__ void cp16(uint32_t dst, const void* src) {
    asm volatile("cp.async.cg.shared.global [%0], [%1], 16;"
                 :: "r"(dst), "l"(src));
}
#define CP_COMMIT() asm volatile("cp.async.commit_group;" ::: "memory")
#define CP_WAIT0()  asm volatile("cp.async.wait_group 0;" ::: "memory")

// top-2 tracker
__device__ __forceinline__ void upd(float s, int code, float& best, float& sec, int& idx) {
    if (s < best) { sec = best; best = s; idx = code; }
    else if (s < sec) { sec = s; }
}

// ---------------------------------------------------------------------------
// Prep: tf32 fragment-ordered codebook, ||c||^2, zero counters
// ---------------------------------------------------------------------------
__global__ void prep_kernel(const float* __restrict__ cb) {
    int k = blockIdx.x * blockDim.x + threadIdx.x;
    if (k >= KCODES) return;
    float v[DIM];
    float s = 0.f;
#pragma unroll
    for (int c = 0; c < DIM; ++c) {
        v[c] = cb[k * DIM + c];
        s = fmaf(v[c], v[c], s);
    }
    g_cnorm[k] = s;
    g_hist[k]  = 0;
    if (k == 0) { g_losssum = 0.f; g_rescue_cnt = 0; }

    const int chunk = k >> 6;
    const int n8    = (k & 63) >> 3;
    const int g     = k & 7;
#pragma unroll
    for (int ks = 0; ks < 8; ++ks) {
#pragma unroll
        for (int t4 = 0; t4 < 4; ++t4) {
            int idx = ((chunk * 8 + n8) * 8 + ks) * 32 + g * 4 + t4;
            g_cbf[idx] = make_float2(to_tf32(v[ks * 8 + t4]),
                                     to_tf32(v[ks * 8 + t4 + 4]));
        }
    }
}

// ---------------------------------------------------------------------------
// tf32 HMMA argmin: 8 warps x 16 tokens; 1-term tf32 mma.sync,
// 2 independent accumulator chains per n8 (even/odd kstep), margin flag.
// smem: cn[1024] (4KB) + 2 chunk buffers of 16KB
// ---------------------------------------------------------------------------
#define SMCN_F   0
#define SMBUF(b) (4096 + (b) * 16384)
#define SM_BYTES (4096 + 2 * 16384)

__global__ void __launch_bounds__(256) argmin_mma_kernel(const float* __restrict__ z) {
    __shared__ __align__(16) char smem[SM_BYTES];
    const uint32_t smb = smem_u32(smem);
    const int tid  = threadIdx.x;
    const int wid  = tid >> 5;
    const int lane = tid & 31;
    const int g    = lane >> 2;
    const int t4   = lane & 3;

    // cn -> smem
    {
        float4* dst = (float4*)(smem + SMCN_F);
        const float4* src = (const float4*)g_cnorm;
        dst[tid] = src[tid];
    }

    // A fragments (tf32): 16 tokens per warp, rows g and g+8
    // per kstep: {z(tokg, d0), z(tokg8, d0), z(tokg, d1), z(tokg8, d1)},
    //            d0 = ks*8 + t4, d1 = d0 + 4
    const int wbase = blockIdx.x * 128 + wid * 16;
    const int b     = wbase >> 10;
    const int hw0   = (wbase & (HW - 1)) + g;
    const float* zb = z + b * (DIM * HW);
    float At[8][4];
#pragma unroll
    for (int ks = 0; ks < 8; ++ks) {
        const int d0 = ks * 8 + t4;
        At[ks][0] = to_tf32(zb[(d0)     * HW + hw0]);
        At[ks][1] = to_tf32(zb[(d0)     * HW + hw0 + 8]);
        At[ks][2] = to_tf32(zb[(d0 + 4) * HW + hw0]);
        At[ks][3] = to_tf32(zb[(d0 + 4) * HW + hw0 + 8]);
    }

    // Prefetch chunk 0 (16KB = 1024 x float4 over 256 threads)
    {
        const char* src = (const char*)g_cbf;
        uint32_t d = smb + SMBUF(0);
#pragma unroll
        for (int i = 0; i < 4; ++i)
            cp16(d + tid * 16 + i * 4096, src + tid * 16 + i * 4096);
        CP_COMMIT();
    }

    float best0 = 3.4e38f, sec0 = 3.4e38f; int idx0 = 0;
    float best1 = 3.4e38f, sec1 = 3.4e38f; int idx1 = 0;

    for (int t = 0; t < NCHUNKS; ++t) {
        const int buf = t & 1;
        CP_WAIT0();
        __syncthreads();

        if (t + 1 < NCHUNKS) {
            const char* src = (const char*)g_cbf + (t + 1) * 16384;
            uint32_t d = smb + SMBUF(1 - buf);
#pragma unroll
            for (int i = 0; i < 4; ++i)
                cp16(d + tid * 16 + i * 4096, src + tid * 16 + i * 4096);
            CP_COMMIT();
        }

        const float2* bq = (const float2*)(smem + SMBUF(buf));
        const float* cn  = (const float*)(smem + SMCN_F);

#pragma unroll
        for (int n8 = 0; n8 < 8; ++n8) {
            // Hoisted B fragments for all 8 K-steps
            float2 Bf[8];
#pragma unroll
            for (int ks = 0; ks < 8; ++ks)
                Bf[ks] = bq[(n8 * 8 + ks) * 32 + lane];
            // Two independent accumulator chains (even / odd ksteps)
            float ae[4] = {0.f, 0.f, 0.f, 0.f};
            float ao[4] = {0.f, 0.f, 0.f, 0.f};
#pragma unroll
            for (int ks = 0; ks < 8; ks += 2) {
                mma1688_tf32(ae, At[ks],     Bf[ks].x,     Bf[ks].y);
                mma1688_tf32(ao, At[ks + 1], Bf[ks + 1].x, Bf[ks + 1].y);
            }
            const int code = t * CHUNK + n8 * 8 + t4 * 2;
            float2 cnv = *(const float2*)(cn + code);
            float s;
            s = fmaf(-2.f, ae[0] + ao[0], cnv.x); upd(s, code,     best0, sec0, idx0);
            s = fmaf(-2.f, ae[1] + ao[1], cnv.y); upd(s, code + 1, best0, sec0, idx0);
            s = fmaf(-2.f, ae[2] + ao[2], cnv.x); upd(s, code,     best1, sec1, idx1);
            s = fmaf(-2.f, ae[3] + ao[3], cnv.y); upd(s, code + 1, best1, sec1, idx1);
        }
        __syncthreads();
    }

    // Reduce top-2 across the 4 lanes of each quad
#pragma unroll
    for (int off = 1; off <= 2; off <<= 1) {
        float ob, os; int oi;
        ob = __shfl_xor_sync(0xffffffffu, best0, off);
        os = __shfl_xor_sync(0xffffffffu, sec0,  off);
        oi = __shfl_xor_sync(0xffffffffu, idx0,  off);
        if (ob < best0 || (ob == best0 && oi < idx0)) { sec0 = fminf(best0, os); best0 = ob; idx0 = oi; }
        else                                          { sec0 = fminf(ob, sec0); }
        ob = __shfl_xor_sync(0xffffffffu, best1, off);
        os = __shfl_xor_sync(0xffffffffu, sec1,  off);
        oi = __shfl_xor_sync(0xffffffffu, idx1,  off);
        if (ob < best1 || (ob == best1 && oi < idx1)) { sec1 = fminf(best1, os); best1 = ob; idx1 = oi; }
        else                                          { sec1 = fminf(ob, sec1); }
    }

    if (t4 == 0) {
        const int tok0 = wbase + g;
        const int tok1 = wbase + g + 8;
        g_idx[tok0] = idx0;
        g_idx[tok1] = idx1;
        if (sec0 - best0 < EPS) { int s = atomicAdd(&g_rescue_cnt, 1); g_rescue[s] = tok0; }
        if (sec1 - best1 < EPS) { int s = atomicAdd(&g_rescue_cnt, 1); g_rescue[s] = tok1; }
    }
}

// ---------------------------------------------------------------------------
// Rescue: exact fp32 argmin for flagged tokens (one warp per token)
// ---------------------------------------------------------------------------
__global__ void __launch_bounds__(128) rescue_kernel(const float* __restrict__ z,
                                                     const float* __restrict__ cb) {
    const int nrs  = g_rescue_cnt;
    const int lane = threadIdx.x & 31;
    const int wpb  = blockDim.x >> 5;
    for (int i = blockIdx.x * wpb + (threadIdx.x >> 5); i < nrs; i += gridDim.x * wpb) {
        const int tok = g_rescue[i];
        const int b   = tok >> 10;
        const int hw  = tok & (HW - 1);
        const float* zp = z + b * (DIM * HW) + hw;
        float zr[DIM];
#pragma unroll
        for (int c = 0; c < DIM; ++c) zr[c] = zp[c << 10];

        float best = 3.4e38f; int bidx = 0x7fffffff;
        for (int k = lane; k < KCODES; k += 32) {
            const float4* cr = (const float4*)(cb + k * DIM);
            float a = 0.f;
#pragma unroll
            for (int c4 = 0; c4 < 16; ++c4) {
                float4 v = cr[c4];
                a = fmaf(zr[4 * c4 + 0], v.x, a);
                a = fmaf(zr[4 * c4 + 1], v.y, a);
                a = fmaf(zr[4 * c4 + 2], v.z, a);
                a = fmaf(zr[4 * c4 + 3], v.w, a);
            }
            float s = fmaf(-2.f, a, g_cnorm[k]);
            if (s < best) { best = s; bidx = k; }
        }
#pragma unroll
        for (int o = 16; o > 0; o >>= 1) {
            float ob = __shfl_down_sync(0xffffffffu, best, o);
            int   oi = __shfl_down_sync(0xffffffffu, bidx, o);
            if (ob < best || (ob == best && oi < bidx)) { best = ob; bidx = oi; }
        }
        if (lane == 0) g_idx[tok] = bidx;
    }
}

// ---------------------------------------------------------------------------
// Epilogue: 4 threads per token (16 channels each) for latency hiding.
// block 256 = 4 subgroups x 64 tokens; grid = NTOK/64 = 1024
// ---------------------------------------------------------------------------
__global__ void __launch_bounds__(256) epilogue_kernel(const float* __restrict__ z,
                                                       const float* __restrict__ cb,
                                                       float* __restrict__ out) {
    const int sub  = threadIdx.x >> 6;           // 0..3 -> channel group
    const int tpos = threadIdx.x & 63;
    const int n    = blockIdx.x * 64 + tpos;
    const int b    = n >> 10;
    const int hw   = n & (HW - 1);
    const int idx  = g_idx[n];
    if (sub == 0) atomicAdd(&g_hist[idx], 1);
    const float4* cbr = (const float4*)(cb + idx * DIM) + sub * 4;
    const int base = b * (DIM * HW) + hw + (sub << 14);   // sub*16 channels

    float acc = 0.f;
#pragma unroll
    for (int j = 0; j < 4; ++j) {
        float4 q = __ldg(cbr + j);
        const int c = j * 4;
        float z0 = z[base + ((c + 0) << 10)];
        float z1 = z[base + ((c + 1) << 10)];
        float z2 = z[base + ((c + 2) << 10)];
        float z3 = z[base + ((c + 3) << 10)];
        float d0 = q.x - z0, d1 = q.y - z1, d2 = q.z - z2, d3 = q.w - z3;
        acc = fmaf(d0, d0, acc);
        acc = fmaf(d1, d1, acc);
        acc = fmaf(d2, d2, acc);
        acc = fmaf(d3, d3, acc);
        out[base + ((c + 0) << 10)] = q.x;
        out[base + ((c + 1) << 10)] = q.y;
        out[base + ((c + 2) << 10)] = q.z;
        out[base + ((c + 3) << 10)] = q.w;
    }
#pragma unroll
    for (int o = 16; o > 0; o >>= 1)
        acc += __shfl_down_sync(0xffffffffu, acc, o);
    __shared__ float red[8];
    if ((threadIdx.x & 31) == 0) red[threadIdx.x >> 5] = acc;
    __syncthreads();
    if (threadIdx.x == 0) {
        float s = 0.f;
#pragma unroll
        for (int w = 0; w < 8; ++w) s += red[w];
        atomicAdd(&g_losssum, s);
    }
}

// ---------------------------------------------------------------------------
// Finalize: perplexity + loss scalars
// ---------------------------------------------------------------------------
__global__ void finalize_kernel(const int* __restrict__ flg,
                                float* __restrict__ out, int write_scalars) {
    const int k = threadIdx.x;
    float e = (float)g_hist[k] * (1.f / (float)NTOK);
    float t = e * logf(e + 1e-10f);
#pragma unroll
    for (int o = 16; o > 0; o >>= 1)
        t += __shfl_down_sync(0xffffffffu, t, o);
    __shared__ float red[32];
    if ((k & 31) == 0) red[k >> 5] = t;
    __syncthreads();
    if (k < 32) {
        float v = red[k];
#pragma unroll
        for (int o = 16; o > 0; o >>= 1)
            v += __shfl_down_sync(0xffffffffu, v, o);
        if (k == 0 && write_scalars) {
            int fbits = *flg;
            float loss = (fbits != 0)
                       ? 1.25f * g_losssum * (1.f / (float)ZQ_ELEMS)
                       : 0.f;
            out[ZQ_ELEMS]     = loss;
            out[ZQ_ELEMS + 1] = expf(-v);
        }
    }
}

// ---------------------------------------------------------------------------
extern "C" void kernel_launch(void* const* d_in, const int* in_sizes, int n_in,
                              void* d_out, int out_size) {
    const float* z   = (const float*)d_in[0];
    const float* cb  = (const float*)d_in[1];
    const int*   flg = (const int*)d_in[3];
    float* out = (float*)d_out;

    prep_kernel<<<8, 128>>>(cb);
    argmin_mma_kernel<<<NTOK / 128, 256>>>(z);
    rescue_kernel<<<128, 128>>>(z, cb);
    epilogue_kernel<<<NTOK / 64, 256>>>(z, cb, out);
    finalize_kernel<<<1, 1024>>>(flg, out, out_size >= ZQ_ELEMS + 2 ? 1 : 0);
}

// round 9
// speedup vs baseline: 1.0710x; 1.0710x over previous
#include <cuda_runtime.h>
#include <cuda_fp16.h>
#include <math.h>
#include <stdint.h>

// Problem constants
#define NB     64
#define DIM    64
#define HW     1024
#define NTOK   65536         // NB*HW
#define KCODES 1024
#define ZQ_ELEMS 4194304     // NB*DIM*HW
#define CHUNK  64            // codes per smem chunk
#define NCHUNKS (KCODES / CHUNK)   // 16
#define EPS    0.15f

// ---------------------------------------------------------------------------
// Device global scratch (no allocation allowed)
// fp16 fragment-ordered codebook: [chunk][n8][kstep(4)][lane] -> uint2
//   reg0 = fp16x2 dims (ks*16 + 2*t4, +1), reg1 = dims (ks*16 + 2*t4 + 8, +9)
//   lane = g*4 + t4, code = chunk*64 + n8*8 + g
// ---------------------------------------------------------------------------
__device__ __align__(16) uint2 g_cbf[NCHUNKS * 8 * 4 * 32];   // 128 KB
__device__ float g_cnorm[KCODES];
__device__ int   g_idx[NTOK];
__device__ int   g_rescue[NTOK];
__device__ int   g_rescue_cnt;
__device__ float g_losssum;
__device__ int   g_hist[KCODES];

// ---------------------------------------------------------------------------
// Helpers
// ---------------------------------------------------------------------------
__device__ __forceinline__ void mma16816_f16(float* c, const uint32_t* a,
                                             uint32_t b0, uint32_t b1) {
    asm volatile(
        "mma.sync.aligned.m16n8k16.row.col.f32.f16.f16.f32 "
        "{%0,%1,%2,%3}, {%4,%5,%6,%7}, {%8,%9}, {%0,%1,%2,%3};"
        : "+f"(c[0]), "+f"(c[1]), "+f"(c[2]), "+f"(c[3])
        : "r"(a[0]), "r"(a[1]), "r"(a[2]), "r"(a[3]), "r"(b0), "r"(b1));
}
__device__ __forceinline__ uint32_t pack_h2(float v0, float v1) {
    __half2 h = __floats2half2_rn(v0, v1);
    return *(uint32_t*)&h;
}
__device__ __forceinline__ uint32_t smem_u32(const void* p) {
    uint32_t a;
    asm("{ .reg .u64 t; cvta.to.shared.u64 t, %1; cvt.u32.u64 %0, t; }"
        : "=r"(a) : "l"(p));
    return a;
}
__device__ __forceinline__ void cp16(uint32_t dst, const void* src) {
    asm volatile("cp.async.cg.shared.global [%0], [%1], 16;"
                 :: "r"(dst), "l"(src));
}
#define CP_COMMIT() asm volatile("cp.async.commit_group;" ::: "memory")
#define CP_WAIT0()  asm volatile("cp.async.wait_group 0;" ::: "memory")

// top-2 tracker
__device__ __forceinline__ void upd(float s, int code, float& best, float& sec, int& idx) {
    if (s < best) { sec = best; best = s; idx = code; }
    else if (s < sec) { sec = s; }
}

// ---------------------------------------------------------------------------
// Prep: fp16 fragment-ordered codebook, ||c||^2, zero counters
// ---------------------------------------------------------------------------
__global__ void prep_kernel(const float* __restrict__ cb) {
    int k = blockIdx.x * blockDim.x + threadIdx.x;
    if (k >= KCODES) return;
    float v[DIM];
    float s = 0.f;
#pragma unroll
    for (int c = 0; c < DIM; ++c) {
        v[c] = cb[k * DIM + c];
        s = fmaf(v[c], v[c], s);
    }
    g_cnorm[k] = s;
    g_hist[k]  = 0;
    if (k == 0) { g_losssum = 0.f; g_rescue_cnt = 0; }

    const int chunk = k >> 6;
    const int n8    = (k & 63) >> 3;
    const int g     = k & 7;
#pragma unroll
    for (int ks = 0; ks < 4; ++ks) {
#pragma unroll
        for (int t4 = 0; t4 < 4; ++t4) {
            int d0 = ks * 16 + t4 * 2;
            int idx = ((chunk * 8 + n8) * 4 + ks) * 32 + g * 4 + t4;
            g_cbf[idx] = make_uint2(pack_h2(v[d0],     v[d0 + 1]),
                                    pack_h2(v[d0 + 8], v[d0 + 9]));
        }
    }
}

// ---------------------------------------------------------------------------
// fp16 HMMA argmin: 8 warps x 16 tokens; 1-term fp16 mma.sync (fp32 accum),
// even/odd kstep accumulator chains, margin flag -> exact fp32 rescue.
// smem: cn[1024] (4KB) + 2 chunk buffers of 8KB = 20KB
// ---------------------------------------------------------------------------
#define SMCN_F   0
#define SMBUF(b) (4096 + (b) * 8192)
#define SM_BYTES (4096 + 2 * 8192)

__global__ void __launch_bounds__(256) argmin_mma_kernel(const float* __restrict__ z) {
    __shared__ __align__(16) char smem[SM_BYTES];
    const uint32_t smb = smem_u32(smem);
    const int tid  = threadIdx.x;
    const int wid  = tid >> 5;
    const int lane = tid & 31;
    const int g    = lane >> 2;
    const int t4   = lane & 3;

    // cn -> smem
    {
        float4* dst = (float4*)(smem + SMCN_F);
        const float4* src = (const float4*)g_cnorm;
        dst[tid] = src[tid];
    }

    // A fragments (fp16): 16 tokens per warp, rows g and g+8
    const int wbase = blockIdx.x * 128 + wid * 16;
    const int b     = wbase >> 10;
    const int hw0   = (wbase & (HW - 1)) + g;
    const float* zb = z + b * (DIM * HW);
    uint32_t Ah[16];
#pragma unroll
    for (int ks = 0; ks < 4; ++ks) {
        int c0 = ks * 16 + t4 * 2;
        Ah[ks * 4 + 0] = pack_h2(zb[(c0)     * HW + hw0],     zb[(c0 + 1) * HW + hw0]);
        Ah[ks * 4 + 1] = pack_h2(zb[(c0)     * HW + hw0 + 8], zb[(c0 + 1) * HW + hw0 + 8]);
        Ah[ks * 4 + 2] = pack_h2(zb[(c0 + 8) * HW + hw0],     zb[(c0 + 9) * HW + hw0]);
        Ah[ks * 4 + 3] = pack_h2(zb[(c0 + 8) * HW + hw0 + 8], zb[(c0 + 9) * HW + hw0 + 8]);
    }

    // Prefetch chunk 0 (8KB = 512 float4 over 256 threads)
    {
        const char* src = (const char*)g_cbf;
        uint32_t d = smb + SMBUF(0);
#pragma unroll
        for (int i = 0; i < 2; ++i)
            cp16(d + tid * 16 + i * 4096, src + tid * 16 + i * 4096);
        CP_COMMIT();
    }

    float best0 = 3.4e38f, sec0 = 3.4e38f; int idx0 = 0;
    float best1 = 3.4e38f, sec1 = 3.4e38f; int idx1 = 0;

    for (int t = 0; t < NCHUNKS; ++t) {
        const int buf = t & 1;
        CP_WAIT0();
        __syncthreads();

        if (t + 1 < NCHUNKS) {
            const char* src = (const char*)g_cbf + (t + 1) * 8192;
            uint32_t d = smb + SMBUF(1 - buf);
#pragma unroll
            for (int i = 0; i < 2; ++i)
                cp16(d + tid * 16 + i * 4096, src + tid * 16 + i * 4096);
            CP_COMMIT();
        }

        const uint2* bq = (const uint2*)(smem + SMBUF(buf));
        const float* cn = (const float*)(smem + SMCN_F);

#pragma unroll
        for (int n8 = 0; n8 < 8; ++n8) {
            // Hoisted B fragments for all 4 K-steps
            uint2 Bf[4];
#pragma unroll
            for (int ks = 0; ks < 4; ++ks)
                Bf[ks] = bq[(n8 * 4 + ks) * 32 + lane];
            // Two independent accumulator chains (even / odd ksteps)
            float ae[4] = {0.f, 0.f, 0.f, 0.f};
            float ao[4] = {0.f, 0.f, 0.f, 0.f};
            mma16816_f16(ae, &Ah[0],  Bf[0].x, Bf[0].y);
            mma16816_f16(ao, &Ah[4],  Bf[1].x, Bf[1].y);
            mma16816_f16(ae, &Ah[8],  Bf[2].x, Bf[2].y);
            mma16816_f16(ao, &Ah[12], Bf[3].x, Bf[3].y);

            const int code = t * CHUNK + n8 * 8 + t4 * 2;
            float2 cnv = *(const float2*)(cn + code);
            float s;
            s = fmaf(-2.f, ae[0] + ao[0], cnv.x); upd(s, code,     best0, sec0, idx0);
            s = fmaf(-2.f, ae[1] + ao[1], cnv.y); upd(s, code + 1, best0, sec0, idx0);
            s = fmaf(-2.f, ae[2] + ao[2], cnv.x); upd(s, code,     best1, sec1, idx1);
            s = fmaf(-2.f, ae[3] + ao[3], cnv.y); upd(s, code + 1, best1, sec1, idx1);
        }
        __syncthreads();
    }

    // Reduce top-2 across the 4 lanes of each quad
#pragma unroll
    for (int off = 1; off <= 2; off <<= 1) {
        float ob, os; int oi;
        ob = __shfl_xor_sync(0xffffffffu, best0, off);
        os = __shfl_xor_sync(0xffffffffu, sec0,  off);
        oi = __shfl_xor_sync(0xffffffffu, idx0,  off);
        if (ob < best0 || (ob == best0 && oi < idx0)) { sec0 = fminf(best0, os); best0 = ob; idx0 = oi; }
        else                                          { sec0 = fminf(ob, sec0); }
        ob = __shfl_xor_sync(0xffffffffu, best1, off);
        os = __shfl_xor_sync(0xffffffffu, sec1,  off);
        oi = __shfl_xor_sync(0xffffffffu, idx1,  off);
        if (ob < best1 || (ob == best1 && oi < idx1)) { sec1 = fminf(best1, os); best1 = ob; idx1 = oi; }
        else                                          { sec1 = fminf(ob, sec1); }
    }

    if (t4 == 0) {
        const int tok0 = wbase + g;
        const int tok1 = wbase + g + 8;
        g_idx[tok0] = idx0;
        g_idx[tok1] = idx1;
        if (sec0 - best0 < EPS) { int s = atomicAdd(&g_rescue_cnt, 1); g_rescue[s] = tok0; }
        if (sec1 - best1 < EPS) { int s = atomicAdd(&g_rescue_cnt, 1); g_rescue[s] = tok1; }
    }
}

// ---------------------------------------------------------------------------
// Rescue: exact fp32 argmin for flagged tokens (one warp per token)
// ---------------------------------------------------------------------------
__global__ void __launch_bounds__(128) rescue_kernel(const float* __restrict__ z,
                                                     const float* __restrict__ cb) {
    const int nrs  = g_rescue_cnt;
    const int lane = threadIdx.x & 31;
    const int wpb  = blockDim.x >> 5;
    for (int i = blockIdx.x * wpb + (threadIdx.x >> 5); i < nrs; i += gridDim.x * wpb) {
        const int tok = g_rescue[i];
        const int b   = tok >> 10;
        const int hw  = tok & (HW - 1);
        const float* zp = z + b * (DIM * HW) + hw;
        float zr[DIM];
#pragma unroll
        for (int c = 0; c < DIM; ++c) zr[c] = zp[c << 10];

        float best = 3.4e38f; int bidx = 0x7fffffff;
        for (int k = lane; k < KCODES; k += 32) {
            const float4* cr = (const float4*)(cb + k * DIM);
            float a = 0.f;
#pragma unroll
            for (int c4 = 0; c4 < 16; ++c4) {
                float4 v = cr[c4];
                a = fmaf(zr[4 * c4 + 0], v.x, a);
                a = fmaf(zr[4 * c4 + 1], v.y, a);
                a = fmaf(zr[4 * c4 + 2], v.z, a);
                a = fmaf(zr[4 * c4 + 3], v.w, a);
            }
            float s = fmaf(-2.f, a, g_cnorm[k]);
            if (s < best) { best = s; bidx = k; }
        }
#pragma unroll
        for (int o = 16; o > 0; o >>= 1) {
            float ob = __shfl_down_sync(0xffffffffu, best, o);
            int   oi = __shfl_down_sync(0xffffffffu, bidx, o);
            if (ob < best || (ob == best && oi < bidx)) { best = ob; bidx = oi; }
        }
        if (lane == 0) g_idx[tok] = bidx;
    }
}

// ---------------------------------------------------------------------------
// Epilogue: 4 threads per token (16 channels each)
// ---------------------------------------------------------------------------
__global__ void __launch_bounds__(256) epilogue_kernel(const float* __restrict__ z,
                                                       const float* __restrict__ cb,
                                                       float* __restrict__ out) {
    const int sub  = threadIdx.x >> 6;           // 0..3 -> channel group
    const int tpos = threadIdx.x & 63;
    const int n    = blockIdx.x * 64 + tpos;
    const int b    = n >> 10;
    const int hw   = n & (HW - 1);
    const int idx  = g_idx[n];
    if (sub == 0) atomicAdd(&g_hist[idx], 1);
    const float4* cbr = (const float4*)(cb + idx * DIM) + sub * 4;
    const int base = b * (DIM * HW) + hw + (sub << 14);   // sub*16 channels

    float acc = 0.f;
#pragma unroll
    for (int j = 0; j < 4; ++j) {
        float4 q = __ldg(cbr + j);
        const int c = j * 4;
        float z0 = z[base + ((c + 0) << 10)];
        float z1 = z[base + ((c + 1) << 10)];
        float z2 = z[base + ((c + 2) << 10)];
        float z3 = z[base + ((c + 3) << 10)];
        float d0 = q.x - z0, d1 = q.y - z1, d2 = q.z - z2, d3 = q.w - z3;
        acc = fmaf(d0, d0, acc);
        acc = fmaf(d1, d1, acc);
        acc = fmaf(d2, d2, acc);
        acc = fmaf(d3, d3, acc);
        out[base + ((c + 0) << 10)] = q.x;
        out[base + ((c + 1) << 10)] = q.y;
        out[base + ((c + 2) << 10)] = q.z;
        out[base + ((c + 3) << 10)] = q.w;
    }
#pragma unroll
    for (int o = 16; o > 0; o >>= 1)
        acc += __shfl_down_sync(0xffffffffu, acc, o);
    __shared__ float red[8];
    if ((threadIdx.x & 31) == 0) red[threadIdx.x >> 5] = acc;
    __syncthreads();
    if (threadIdx.x == 0) {
        float s = 0.f;
#pragma unroll
        for (int w = 0; w < 8; ++w) s += red[w];
        atomicAdd(&g_losssum, s);
    }
}

// ---------------------------------------------------------------------------
// Finalize: perplexity + loss scalars
// ---------------------------------------------------------------------------
__global__ void finalize_kernel(const int* __restrict__ flg,
                                float* __restrict__ out, int write_scalars) {
    const int k = threadIdx.x;
    float e = (float)g_hist[k] * (1.f / (float)NTOK);
    float t = e * logf(e + 1e-10f);
#pragma unroll
    for (int o = 16; o > 0; o >>= 1)
        t += __shfl_down_sync(0xffffffffu, t, o);
    __shared__ float red[32];
    if ((k & 31) == 0) red[k >> 5] = t;
    __syncthreads();
    if (k < 32) {
        float v = red[k];
#pragma unroll
        for (int o = 16; o > 0; o >>= 1)
            v += __shfl_down_sync(0xffffffffu, v, o);
        if (k == 0 && write_scalars) {
            int fbits = *flg;
            float loss = (fbits != 0)
                       ? 1.25f * g_losssum * (1.f / (float)ZQ_ELEMS)
                       : 0.f;
            out[ZQ_ELEMS]     = loss;
            out[ZQ_ELEMS + 1] = expf(-v);
        }
    }
}

// ---------------------------------------------------------------------------
extern "C" void kernel_launch(void* const* d_in, const int* in_sizes, int n_in,
                              void* d_out, int out_size) {
    const float* z   = (const float*)d_in[0];
    const float* cb  = (const float*)d_in[1];
    const int*   flg = (const int*)d_in[3];
    float* out = (float*)d_out;

    prep_kernel<<<8, 128>>>(cb);
    argmin_mma_kernel<<<NTOK / 128, 256>>>(z);
    rescue_kernel<<<256, 128>>>(z, cb);
    epilogue_kernel<<<NTOK / 64, 256>>>(z, cb, out);
    finalize_kernel<<<1, 1024>>>(flg, out, out_size >= ZQ_ELEMS + 2 ? 1 : 0);
}

// round 10
// speedup vs baseline: 1.8568x; 1.7336x over previous
#include <cuda_runtime.h>
#include <cuda_fp16.h>
#include <math.h>
#include <stdint.h>

// Problem constants
#define NB     64
#define DIM    64
#define HW     1024
#define NTOK   65536         // NB*HW
#define KCODES 1024
#define ZQ_ELEMS 4194304     // NB*DIM*HW
#define CHUNK  64            // codes per smem chunk
#define NCHUNKS (KCODES / CHUNK)   // 16
#define EPS    0.065f

// ---------------------------------------------------------------------------
// Device global scratch (no allocation allowed)
// fp16 fragment-ordered codebook: [chunk][n8][kstep(4)][lane] -> uint2
//   reg0 = fp16x2 dims (ks*16 + 2*t4, +1), reg1 = dims (ks*16 + 2*t4 + 8, +9)
//   lane = g*4 + t4, code = chunk*64 + n8*8 + g
// ---------------------------------------------------------------------------
__device__ __align__(16) uint2 g_cbf[NCHUNKS * 8 * 4 * 32];   // 128 KB
__device__ float g_cnorm[KCODES];
__device__ int   g_idx[NTOK];
__device__ int   g_rescue[NTOK];
__device__ int   g_rescue_cnt;
__device__ float g_losssum;
__device__ int   g_hist[KCODES];

// ---------------------------------------------------------------------------
// Helpers
// ---------------------------------------------------------------------------
__device__ __forceinline__ void mma16816_f16(float* c, const uint32_t* a,
                                             uint32_t b0, uint32_t b1) {
    asm volatile(
        "mma.sync.aligned.m16n8k16.row.col.f32.f16.f16.f32 "
        "{%0,%1,%2,%3}, {%4,%5,%6,%7}, {%8,%9}, {%0,%1,%2,%3};"
        : "+f"(c[0]), "+f"(c[1]), "+f"(c[2]), "+f"(c[3])
        : "r"(a[0]), "r"(a[1]), "r"(a[2]), "r"(a[3]), "r"(b0), "r"(b1));
}
__device__ __forceinline__ uint32_t pack_h2(float v0, float v1) {
    __half2 h = __floats2half2_rn(v0, v1);
    return *(uint32_t*)&h;
}
__device__ __forceinline__ uint32_t smem_u32(const void* p) {
    uint32_t a;
    asm("{ .reg .u64 t; cvta.to.shared.u64 t, %1; cvt.u32.u64 %0, t; }"
        : "=r"(a) : "l"(p));
    return a;
}
__device__ __forceinline__ void cp16(uint32_t dst, const void* src) {
    asm volatile("cp.async.cg.shared.global [%0], [%1], 16;"
                 :: "r"(dst), "l"(src));
}
#define CP_COMMIT() asm volatile("cp.async.commit_group;" ::: "memory")
#define CP_WAIT0()  asm volatile("cp.async.wait_group 0;" ::: "memory")

// top-2 tracker
__device__ __forceinline__ void upd(float s, int code, float& best, float& sec, int& idx) {
    if (s < best) { sec = best; best = s; idx = code; }
    else if (s < sec) { sec = s; }
}

// ---------------------------------------------------------------------------
// Prep: fp16 fragment-ordered codebook, ||c||^2, zero counters
// ---------------------------------------------------------------------------
__global__ void prep_kernel(const float* __restrict__ cb) {
    int k = blockIdx.x * blockDim.x + threadIdx.x;
    if (k >= KCODES) return;
    float v[DIM];
    float s = 0.f;
#pragma unroll
    for (int c = 0; c < DIM; ++c) {
        v[c] = cb[k * DIM + c];
        s = fmaf(v[c], v[c], s);
    }
    g_cnorm[k] = s;
    g_hist[k]  = 0;
    if (k == 0) { g_losssum = 0.f; g_rescue_cnt = 0; }

    const int chunk = k >> 6;
    const int n8    = (k & 63) >> 3;
    const int g     = k & 7;
#pragma unroll
    for (int ks = 0; ks < 4; ++ks) {
#pragma unroll
        for (int t4 = 0; t4 < 4; ++t4) {
            int d0 = ks * 16 + t4 * 2;
            int idx = ((chunk * 8 + n8) * 4 + ks) * 32 + g * 4 + t4;
            g_cbf[idx] = make_uint2(pack_h2(v[d0],     v[d0 + 1]),
                                    pack_h2(v[d0 + 8], v[d0 + 9]));
        }
    }
}

// ---------------------------------------------------------------------------
// fp16 HMMA argmin: 8 warps x 16 tokens; 1-term fp16 mma.sync (fp32 accum),
// even/odd kstep accumulator chains, margin flag -> exact fp32 rescue.
// smem: cn[1024] (4KB) + 2 chunk buffers of 8KB = 20KB
// ---------------------------------------------------------------------------
#define SMCN_F   0
#define SMBUF(b) (4096 + (b) * 8192)
#define SM_BYTES (4096 + 2 * 8192)

__global__ void __launch_bounds__(256) argmin_mma_kernel(const float* __restrict__ z) {
    __shared__ __align__(16) char smem[SM_BYTES];
    const uint32_t smb = smem_u32(smem);
    const int tid  = threadIdx.x;
    const int wid  = tid >> 5;
    const int lane = tid & 31;
    const int g    = lane >> 2;
    const int t4   = lane & 3;

    // cn -> smem
    {
        float4* dst = (float4*)(smem + SMCN_F);
        const float4* src = (const float4*)g_cnorm;
        dst[tid] = src[tid];
    }

    // A fragments (fp16): 16 tokens per warp, rows g and g+8
    const int wbase = blockIdx.x * 128 + wid * 16;
    const int b     = wbase >> 10;
    const int hw0   = (wbase & (HW - 1)) + g;
    const float* zb = z + b * (DIM * HW);
    uint32_t Ah[16];
#pragma unroll
    for (int ks = 0; ks < 4; ++ks) {
        int c0 = ks * 16 + t4 * 2;
        Ah[ks * 4 + 0] = pack_h2(zb[(c0)     * HW + hw0],     zb[(c0 + 1) * HW + hw0]);
        Ah[ks * 4 + 1] = pack_h2(zb[(c0)     * HW + hw0 + 8], zb[(c0 + 1) * HW + hw0 + 8]);
        Ah[ks * 4 + 2] = pack_h2(zb[(c0 + 8) * HW + hw0],     zb[(c0 + 9) * HW + hw0]);
        Ah[ks * 4 + 3] = pack_h2(zb[(c0 + 8) * HW + hw0 + 8], zb[(c0 + 9) * HW + hw0 + 8]);
    }

    // Prefetch chunk 0 (8KB = 512 float4 over 256 threads)
    {
        const char* src = (const char*)g_cbf;
        uint32_t d = smb + SMBUF(0);
#pragma unroll
        for (int i = 0; i < 2; ++i)
            cp16(d + tid * 16 + i * 4096, src + tid * 16 + i * 4096);
        CP_COMMIT();
    }

    float best0 = 3.4e38f, sec0 = 3.4e38f; int idx0 = 0;
    float best1 = 3.4e38f, sec1 = 3.4e38f; int idx1 = 0;

    for (int t = 0; t < NCHUNKS; ++t) {
        const int buf = t & 1;
        CP_WAIT0();
        __syncthreads();

        if (t + 1 < NCHUNKS) {
            const char* src = (const char*)g_cbf + (t + 1) * 8192;
            uint32_t d = smb + SMBUF(1 - buf);
#pragma unroll
            for (int i = 0; i < 2; ++i)
                cp16(d + tid * 16 + i * 4096, src + tid * 16 + i * 4096);
            CP_COMMIT();
        }

        const uint2* bq = (const uint2*)(smem + SMBUF(buf));
        const float* cn = (const float*)(smem + SMCN_F);

#pragma unroll
        for (int n8 = 0; n8 < 8; ++n8) {
            // Hoisted B fragments for all 4 K-steps
            uint2 Bf[4];
#pragma unroll
            for (int ks = 0; ks < 4; ++ks)
                Bf[ks] = bq[(n8 * 4 + ks) * 32 + lane];
            // Two independent accumulator chains (even / odd ksteps)
            float ae[4] = {0.f, 0.f, 0.f, 0.f};
            float ao[4] = {0.f, 0.f, 0.f, 0.f};
            mma16816_f16(ae, &Ah[0],  Bf[0].x, Bf[0].y);
            mma16816_f16(ao, &Ah[4],  Bf[1].x, Bf[1].y);
            mma16816_f16(ae, &Ah[8],  Bf[2].x, Bf[2].y);
            mma16816_f16(ao, &Ah[12], Bf[3].x, Bf[3].y);

            const int code = t * CHUNK + n8 * 8 + t4 * 2;
            float2 cnv = *(const float2*)(cn + code);
            float s;
            s = fmaf(-2.f, ae[0] + ao[0], cnv.x); upd(s, code,     best0, sec0, idx0);
            s = fmaf(-2.f, ae[1] + ao[1], cnv.y); upd(s, code + 1, best0, sec0, idx0);
            s = fmaf(-2.f, ae[2] + ao[2], cnv.x); upd(s, code,     best1, sec1, idx1);
            s = fmaf(-2.f, ae[3] + ao[3], cnv.y); upd(s, code + 1, best1, sec1, idx1);
        }
        __syncthreads();
    }

    // Reduce top-2 across the 4 lanes of each quad
#pragma unroll
    for (int off = 1; off <= 2; off <<= 1) {
        float ob, os; int oi;
        ob = __shfl_xor_sync(0xffffffffu, best0, off);
        os = __shfl_xor_sync(0xffffffffu, sec0,  off);
        oi = __shfl_xor_sync(0xffffffffu, idx0,  off);
        if (ob < best0 || (ob == best0 && oi < idx0)) { sec0 = fminf(best0, os); best0 = ob; idx0 = oi; }
        else                                          { sec0 = fminf(ob, sec0); }
        ob = __shfl_xor_sync(0xffffffffu, best1, off);
        os = __shfl_xor_sync(0xffffffffu, sec1,  off);
        oi = __shfl_xor_sync(0xffffffffu, idx1,  off);
        if (ob < best1 || (ob == best1 && oi < idx1)) { sec1 = fminf(best1, os); best1 = ob; idx1 = oi; }
        else                                          { sec1 = fminf(ob, sec1); }
    }

    if (t4 == 0) {
        const int tok0 = wbase + g;
        const int tok1 = wbase + g + 8;
        g_idx[tok0] = idx0;
        g_idx[tok1] = idx1;
        if (sec0 - best0 < EPS) { int s = atomicAdd(&g_rescue_cnt, 1); g_rescue[s] = tok0; }
        if (sec1 - best1 < EPS) { int s = atomicAdd(&g_rescue_cnt, 1); g_rescue[s] = tok1; }
    }
}

// ---------------------------------------------------------------------------
// Rescue: exact fp32 argmin for flagged tokens (one warp per token)
// ---------------------------------------------------------------------------
__global__ void __launch_bounds__(128) rescue_kernel(const float* __restrict__ z,
                                                     const float* __restrict__ cb) {
    const int nrs  = g_rescue_cnt;
    const int lane = threadIdx.x & 31;
    const int wpb  = blockDim.x >> 5;
    for (int i = blockIdx.x * wpb + (threadIdx.x >> 5); i < nrs; i += gridDim.x * wpb) {
        const int tok = g_rescue[i];
        const int b   = tok >> 10;
        const int hw  = tok & (HW - 1);
        const float* zp = z + b * (DIM * HW) + hw;
        float zr[DIM];
#pragma unroll
        for (int c = 0; c < DIM; ++c) zr[c] = zp[c << 10];

        float best = 3.4e38f; int bidx = 0x7fffffff;
        for (int k = lane; k < KCODES; k += 32) {
            const float4* cr = (const float4*)(cb + k * DIM);
            float a = 0.f;
#pragma unroll
            for (int c4 = 0; c4 < 16; ++c4) {
                float4 v = cr[c4];
                a = fmaf(zr[4 * c4 + 0], v.x, a);
                a = fmaf(zr[4 * c4 + 1], v.y, a);
                a = fmaf(zr[4 * c4 + 2], v.z, a);
                a = fmaf(zr[4 * c4 + 3], v.w, a);
            }
            float s = fmaf(-2.f, a, g_cnorm[k]);
            if (s < best) { best = s; bidx = k; }
        }
#pragma unroll
        for (int o = 16; o > 0; o >>= 1) {
            float ob = __shfl_down_sync(0xffffffffu, best, o);
            int   oi = __shfl_down_sync(0xffffffffu, bidx, o);
            if (ob < best || (ob == best && oi < bidx)) { best = ob; bidx = oi; }
        }
        if (lane == 0) g_idx[tok] = bidx;
    }
}

// ---------------------------------------------------------------------------
// Epilogue: 4 threads per token (16 channels each)
// ---------------------------------------------------------------------------
__global__ void __launch_bounds__(256) epilogue_kernel(const float* __restrict__ z,
                                                       const float* __restrict__ cb,
                                                       float* __restrict__ out) {
    const int sub  = threadIdx.x >> 6;           // 0..3 -> channel group
    const int tpos = threadIdx.x & 63;
    const int n    = blockIdx.x * 64 + tpos;
    const int b    = n >> 10;
    const int hw   = n & (HW - 1);
    const int idx  = g_idx[n];
    if (sub == 0) atomicAdd(&g_hist[idx], 1);
    const float4* cbr = (const float4*)(cb + idx * DIM) + sub * 4;
    const int base = b * (DIM * HW) + hw + (sub << 14);   // sub*16 channels

    float acc = 0.f;
#pragma unroll
    for (int j = 0; j < 4; ++j) {
        float4 q = __ldg(cbr + j);
        const int c = j * 4;
        float z0 = z[base + ((c + 0) << 10)];
        float z1 = z[base + ((c + 1) << 10)];
        float z2 = z[base + ((c + 2) << 10)];
        float z3 = z[base + ((c + 3) << 10)];
        float d0 = q.x - z0, d1 = q.y - z1, d2 = q.z - z2, d3 = q.w - z3;
        acc = fmaf(d0, d0, acc);
        acc = fmaf(d1, d1, acc);
        acc = fmaf(d2, d2, acc);
        acc = fmaf(d3, d3, acc);
        out[base + ((c + 0) << 10)] = q.x;
        out[base + ((c + 1) << 10)] = q.y;
        out[base + ((c + 2) << 10)] = q.z;
        out[base + ((c + 3) << 10)] = q.w;
    }
#pragma unroll
    for (int o = 16; o > 0; o >>= 1)
        acc += __shfl_down_sync(0xffffffffu, acc, o);
    __shared__ float red[8];
    if ((threadIdx.x & 31) == 0) red[threadIdx.x >> 5] = acc;
    __syncthreads();
    if (threadIdx.x == 0) {
        float s = 0.f;
#pragma unroll
        for (int w = 0; w < 8; ++w) s += red[w];
        atomicAdd(&g_losssum, s);
    }
}

// ---------------------------------------------------------------------------
// Finalize: perplexity + loss scalars
// ---------------------------------------------------------------------------
__global__ void finalize_kernel(const int* __restrict__ flg,
                                float* __restrict__ out, int write_scalars) {
    const int k = threadIdx.x;
    float e = (float)g_hist[k] * (1.f / (float)NTOK);
    float t = e * logf(e + 1e-10f);
#pragma unroll
    for (int o = 16; o > 0; o >>= 1)
        t += __shfl_down_sync(0xffffffffu, t, o);
    __shared__ float red[32];
    if ((k & 31) == 0) red[k >> 5] = t;
    __syncthreads();
    if (k < 32) {
        float v = red[k];
#pragma unroll
        for (int o = 16; o > 0; o >>= 1)
            v += __shfl_down_sync(0xffffffffu, v, o);
        if (k == 0 && write_scalars) {
            int fbits = *flg;
            float loss = (fbits != 0)
                       ? 1.25f * g_losssum * (1.f / (float)ZQ_ELEMS)
                       : 0.f;
            out[ZQ_ELEMS]     = loss;
            out[ZQ_ELEMS + 1] = expf(-v);
        }
    }
}

// ---------------------------------------------------------------------------
extern "C" void kernel_launch(void* const* d_in, const int* in_sizes, int n_in,
                              void* d_out, int out_size) {
    const float* z   = (const float*)d_in[0];
    const float* cb  = (const float*)d_in[1];
    const int*   flg = (const int*)d_in[3];
    float* out = (float*)d_out;

    prep_kernel<<<8, 128>>>(cb);
    argmin_mma_kernel<<<NTOK / 128, 256>>>(z);
    rescue_kernel<<<256, 128>>>(z, cb);
    epilogue_kernel<<<NTOK / 64, 256>>>(z, cb, out);
    finalize_kernel<<<1, 1024>>>(flg, out, out_size >= ZQ_ELEMS + 2 ? 1 : 0);
}

// round 11
// speedup vs baseline: 2.6352x; 1.4193x over previous
#include <cuda_runtime.h>
#include <cuda_fp16.h>
#include <math.h>
#include <stdint.h>

// Problem constants
#define NB     64
#define DIM    64
#define HW     1024
#define NTOK   65536         // NB*HW
#define KCODES 1024
#define ZQ_ELEMS 4194304     // NB*DIM*HW
#define CHUNK  64            // codes per smem chunk (argmin)
#define NCHUNKS (KCODES / CHUNK)   // 16
#define EPS    0.065f

// ---------------------------------------------------------------------------
// Device global scratch (no allocation allowed)
// ---------------------------------------------------------------------------
__device__ __align__(16) uint2 g_cbf[NCHUNKS * 8 * 4 * 32];   // fp16 fragments, 128 KB
__device__ __align__(16) float g_cbT[DIM * KCODES];           // transposed fp32, 256 KB
__device__ __align__(16) float g_cnorm[KCODES];
__device__ int   g_idx[NTOK];
__device__ int   g_rescue[NTOK];
__device__ int   g_rescue_cnt;
__device__ float g_losssum;
__device__ int   g_hist[KCODES];

// ---------------------------------------------------------------------------
// Helpers
// ---------------------------------------------------------------------------
__device__ __forceinline__ void mma16816_f16(float* c, const uint32_t* a,
                                             uint32_t b0, uint32_t b1) {
    asm volatile(
        "mma.sync.aligned.m16n8k16.row.col.f32.f16.f16.f32 "
        "{%0,%1,%2,%3}, {%4,%5,%6,%7}, {%8,%9}, {%0,%1,%2,%3};"
        : "+f"(c[0]), "+f"(c[1]), "+f"(c[2]), "+f"(c[3])
        : "r"(a[0]), "r"(a[1]), "r"(a[2]), "r"(a[3]), "r"(b0), "r"(b1));
}
__device__ __forceinline__ uint32_t pack_h2(float v0, float v1) {
    __half2 h = __floats2half2_rn(v0, v1);
    return *(uint32_t*)&h;
}
__device__ __forceinline__ uint32_t smem_u32(const void* p) {
    uint32_t a;
    asm("{ .reg .u64 t; cvta.to.shared.u64 t, %1; cvt.u32.u64 %0, t; }"
        : "=r"(a) : "l"(p));
    return a;
}
__device__ __forceinline__ void cp16(uint32_t dst, const void* src) {
    asm volatile("cp.async.cg.shared.global [%0], [%1], 16;"
                 :: "r"(dst), "l"(src));
}
#define CP_COMMIT() asm volatile("cp.async.commit_group;" ::: "memory")
#define CP_WAIT0()  asm volatile("cp.async.wait_group 0;" ::: "memory")

// top-2 tracker
__device__ __forceinline__ void upd(float s, int code, float& best, float& sec, int& idx) {
    if (s < best) { sec = best; best = s; idx = code; }
    else if (s < sec) { sec = s; }
}

// ---------------------------------------------------------------------------
// Prep: fp16 fragment codebook + transposed fp32 codebook, ||c||^2, counters
// ---------------------------------------------------------------------------
__global__ void prep_kernel(const float* __restrict__ cb) {
    int k = blockIdx.x * blockDim.x + threadIdx.x;
    if (k >= KCODES) return;
    float v[DIM];
    float s = 0.f;
#pragma unroll
    for (int c = 0; c < DIM; ++c) {
        v[c] = cb[k * DIM + c];
        s = fmaf(v[c], v[c], s);
        g_cbT[c * KCODES + k] = v[c];      // coalesced across k per c
    }
    g_cnorm[k] = s;
    g_hist[k]  = 0;
    if (k == 0) { g_losssum = 0.f; g_rescue_cnt = 0; }

    const int chunk = k >> 6;
    const int n8    = (k & 63) >> 3;
    const int g     = k & 7;
#pragma unroll
    for (int ks = 0; ks < 4; ++ks) {
#pragma unroll
        for (int t4 = 0; t4 < 4; ++t4) {
            int d0 = ks * 16 + t4 * 2;
            int idx = ((chunk * 8 + n8) * 4 + ks) * 32 + g * 4 + t4;
            g_cbf[idx] = make_uint2(pack_h2(v[d0],     v[d0 + 1]),
                                    pack_h2(v[d0 + 8], v[d0 + 9]));
        }
    }
}

// ---------------------------------------------------------------------------
// fp16 HMMA argmin (unchanged from R10): 8 warps x 16 tokens; 1-term fp16
// mma.sync (fp32 accum), margin flag -> exact fp32 rescue.
// ---------------------------------------------------------------------------
#define SMCN_F   0
#define SMBUF(b) (4096 + (b) * 8192)
#define SM_BYTES (4096 + 2 * 8192)

__global__ void __launch_bounds__(256) argmin_mma_kernel(const float* __restrict__ z) {
    __shared__ __align__(16) char smem[SM_BYTES];
    const uint32_t smb = smem_u32(smem);
    const int tid  = threadIdx.x;
    const int wid  = tid >> 5;
    const int lane = tid & 31;
    const int g    = lane >> 2;
    const int t4   = lane & 3;

    {
        float4* dst = (float4*)(smem + SMCN_F);
        const float4* src = (const float4*)g_cnorm;
        dst[tid] = src[tid];
    }

    const int wbase = blockIdx.x * 128 + wid * 16;
    const int b     = wbase >> 10;
    const int hw0   = (wbase & (HW - 1)) + g;
    const float* zb = z + b * (DIM * HW);
    uint32_t Ah[16];
#pragma unroll
    for (int ks = 0; ks < 4; ++ks) {
        int c0 = ks * 16 + t4 * 2;
        Ah[ks * 4 + 0] = pack_h2(zb[(c0)     * HW + hw0],     zb[(c0 + 1) * HW + hw0]);
        Ah[ks * 4 + 1] = pack_h2(zb[(c0)     * HW + hw0 + 8], zb[(c0 + 1) * HW + hw0 + 8]);
        Ah[ks * 4 + 2] = pack_h2(zb[(c0 + 8) * HW + hw0],     zb[(c0 + 9) * HW + hw0]);
        Ah[ks * 4 + 3] = pack_h2(zb[(c0 + 8) * HW + hw0 + 8], zb[(c0 + 9) * HW + hw0 + 8]);
    }

    {
        const char* src = (const char*)g_cbf;
        uint32_t d = smb + SMBUF(0);
#pragma unroll
        for (int i = 0; i < 2; ++i)
            cp16(d + tid * 16 + i * 4096, src + tid * 16 + i * 4096);
        CP_COMMIT();
    }

    float best0 = 3.4e38f, sec0 = 3.4e38f; int idx0 = 0;
    float best1 = 3.4e38f, sec1 = 3.4e38f; int idx1 = 0;

    for (int t = 0; t < NCHUNKS; ++t) {
        const int buf = t & 1;
        CP_WAIT0();
        __syncthreads();

        if (t + 1 < NCHUNKS) {
            const char* src = (const char*)g_cbf + (t + 1) * 8192;
            uint32_t d = smb + SMBUF(1 - buf);
#pragma unroll
            for (int i = 0; i < 2; ++i)
                cp16(d + tid * 16 + i * 4096, src + tid * 16 + i * 4096);
            CP_COMMIT();
        }

        const uint2* bq = (const uint2*)(smem + SMBUF(buf));
        const float* cn = (const float*)(smem + SMCN_F);

#pragma unroll
        for (int n8 = 0; n8 < 8; ++n8) {
            uint2 Bf[4];
#pragma unroll
            for (int ks = 0; ks < 4; ++ks)
                Bf[ks] = bq[(n8 * 4 + ks) * 32 + lane];
            float ae[4] = {0.f, 0.f, 0.f, 0.f};
            float ao[4] = {0.f, 0.f, 0.f, 0.f};
            mma16816_f16(ae, &Ah[0],  Bf[0].x, Bf[0].y);
            mma16816_f16(ao, &Ah[4],  Bf[1].x, Bf[1].y);
            mma16816_f16(ae, &Ah[8],  Bf[2].x, Bf[2].y);
            mma16816_f16(ao, &Ah[12], Bf[3].x, Bf[3].y);

            const int code = t * CHUNK + n8 * 8 + t4 * 2;
            float2 cnv = *(const float2*)(cn + code);
            float s;
            s = fmaf(-2.f, ae[0] + ao[0], cnv.x); upd(s, code,     best0, sec0, idx0);
            s = fmaf(-2.f, ae[1] + ao[1], cnv.y); upd(s, code + 1, best0, sec0, idx0);
            s = fmaf(-2.f, ae[2] + ao[2], cnv.x); upd(s, code,     best1, sec1, idx1);
            s = fmaf(-2.f, ae[3] + ao[3], cnv.y); upd(s, code + 1, best1, sec1, idx1);
        }
        __syncthreads();
    }

#pragma unroll
    for (int off = 1; off <= 2; off <<= 1) {
        float ob, os; int oi;
        ob = __shfl_xor_sync(0xffffffffu, best0, off);
        os = __shfl_xor_sync(0xffffffffu, sec0,  off);
        oi = __shfl_xor_sync(0xffffffffu, idx0,  off);
        if (ob < best0 || (ob == best0 && oi < idx0)) { sec0 = fminf(best0, os); best0 = ob; idx0 = oi; }
        else                                          { sec0 = fminf(ob, sec0); }
        ob = __shfl_xor_sync(0xffffffffu, best1, off);
        os = __shfl_xor_sync(0xffffffffu, sec1,  off);
        oi = __shfl_xor_sync(0xffffffffu, idx1,  off);
        if (ob < best1 || (ob == best1 && oi < idx1)) { sec1 = fminf(best1, os); best1 = ob; idx1 = oi; }
        else                                          { sec1 = fminf(ob, sec1); }
    }

    if (t4 == 0) {
        const int tok0 = wbase + g;
        const int tok1 = wbase + g + 8;
        g_idx[tok0] = idx0;
        g_idx[tok1] = idx1;
        if (sec0 - best0 < EPS) { int s = atomicAdd(&g_rescue_cnt, 1); g_rescue[s] = tok0; }
        if (sec1 - best1 < EPS) { int s = atomicAdd(&g_rescue_cnt, 1); g_rescue[s] = tok1; }
    }
}

// ---------------------------------------------------------------------------
// Rescue v2: smem-chunked exact fp32 argmin.
// 32 tokens/block (z staged in smem), codebook streamed as 8 transposed
// chunks of 128 codes (32 KB). One warp owns 4 tokens; each lane scans 4
// codes per chunk via conflict-free LDS.128, z via broadcast LDS.
// Identical fmaf ordering to the reference-exact path -> bitwise-same argmin.
// ---------------------------------------------------------------------------
__global__ void __launch_bounds__(256) rescue_kernel(const float* __restrict__ z) {
    __shared__ __align__(16) float smZ[32][64];    // 8 KB
    __shared__ __align__(16) float smC[64][128];   // 32 KB, [c][k within chunk]
    const int cnt  = g_rescue_cnt;
    const int tid  = threadIdx.x;
    const int wid  = tid >> 5;
    const int lane = tid & 31;

    for (int base = blockIdx.x * 32; base < cnt; base += gridDim.x * 32) {
        __syncthreads();   // smZ reuse across base iterations
        // Stage 32 tokens' z vectors (clamped gather; duplicates are idempotent)
#pragma unroll
        for (int j = 0; j < 8; ++j) {
            int li = tid * 8 + j;              // 0..2047
            int t  = li >> 6;
            int c  = li & 63;
            int gi = base + t;
            int tok = g_rescue[gi < cnt ? gi : cnt - 1];
            int b = tok >> 10, hw = tok & (HW - 1);
            smZ[t][c] = z[b * (DIM * HW) + c * HW + hw];
        }

        float best[4] = {3.4e38f, 3.4e38f, 3.4e38f, 3.4e38f};
        int   bidx[4] = {0, 0, 0, 0};

        for (int ch = 0; ch < 8; ++ch) {
            __syncthreads();   // previous chunk consumed / smZ staged
            // Load chunk: smC[c][0..127] = g_cbT[c*1024 + ch*128 ...]
#pragma unroll
            for (int i = 0; i < 8; ++i) {
                int li = tid + i * 256;        // 0..2047 float4 slots
                int r  = li >> 5;              // c row
                int cc = li & 31;              // float4 col within chunk
                ((float4*)smC)[li] = ((const float4*)g_cbT)[r * 256 + ch * 32 + cc];
            }
            __syncthreads();

#pragma unroll
            for (int t = 0; t < 4; ++t) {
                const float* zt = smZ[wid * 4 + t];
                float a0 = 0.f, a1 = 0.f, a2 = 0.f, a3 = 0.f;
#pragma unroll
                for (int c = 0; c < DIM; ++c) {
                    float zc = zt[c];                                  // broadcast
                    float4 cv = *((const float4*)&smC[c][lane * 4]);   // conflict-free
                    a0 = fmaf(zc, cv.x, a0);
                    a1 = fmaf(zc, cv.y, a1);
                    a2 = fmaf(zc, cv.z, a2);
                    a3 = fmaf(zc, cv.w, a3);
                }
                const int k0 = ch * 128 + lane * 4;
                float4 cn = *((const float4*)&g_cnorm[k0]);
                float s;
                s = fmaf(-2.f, a0, cn.x); if (s < best[t]) { best[t] = s; bidx[t] = k0;     }
                s = fmaf(-2.f, a1, cn.y); if (s < best[t]) { best[t] = s; bidx[t] = k0 + 1; }
                s = fmaf(-2.f, a2, cn.z); if (s < best[t]) { best[t] = s; bidx[t] = k0 + 2; }
                s = fmaf(-2.f, a3, cn.w); if (s < best[t]) { best[t] = s; bidx[t] = k0 + 3; }
            }
        }

        // Lexicographic (value, index) reduce over lanes -> first-occurrence ties
#pragma unroll
        for (int t = 0; t < 4; ++t) {
            float b_ = best[t]; int i_ = bidx[t];
#pragma unroll
            for (int o = 16; o > 0; o >>= 1) {
                float ob = __shfl_down_sync(0xffffffffu, b_, o);
                int   oi = __shfl_down_sync(0xffffffffu, i_, o);
                if (ob < b_ || (ob == b_ && oi < i_)) { b_ = ob; i_ = oi; }
            }
            if (lane == 0) {
                int gi = base + wid * 4 + t;
                if (gi < cnt) g_idx[g_rescue[gi]] = i_;
            }
        }
    }
}

// ---------------------------------------------------------------------------
// Epilogue: 4 threads per token (16 channels each); codebook loads hoisted
// ---------------------------------------------------------------------------
__global__ void __launch_bounds__(256) epilogue_kernel(const float* __restrict__ z,
                                                       const float* __restrict__ cb,
                                                       float* __restrict__ out) {
    const int sub  = threadIdx.x >> 6;           // 0..3 -> channel group
    const int tpos = threadIdx.x & 63;
    const int n    = blockIdx.x * 64 + tpos;
    const int b    = n >> 10;
    const int hw   = n & (HW - 1);
    const int idx  = g_idx[n];
    if (sub == 0) atomicAdd(&g_hist[idx], 1);
    const float4* cbr = (const float4*)(cb + idx * DIM) + sub * 4;
    const int base = b * (DIM * HW) + hw + (sub << 14);   // sub*16 channels

    // Hoist all codebook loads for MLP
    float4 q[4];
#pragma unroll
    for (int j = 0; j < 4; ++j) q[j] = __ldg(cbr + j);

    float acc = 0.f;
#pragma unroll
    for (int j = 0; j < 4; ++j) {
        const int c = j * 4;
        float z0 = z[base + ((c + 0) << 10)];
        float z1 = z[base + ((c + 1) << 10)];
        float z2 = z[base + ((c + 2) << 10)];
        float z3 = z[base + ((c + 3) << 10)];
        float d0 = q[j].x - z0, d1 = q[j].y - z1, d2 = q[j].z - z2, d3 = q[j].w - z3;
        acc = fmaf(d0, d0, acc);
        acc = fmaf(d1, d1, acc);
        acc = fmaf(d2, d2, acc);
        acc = fmaf(d3, d3, acc);
        out[base + ((c + 0) << 10)] = q[j].x;
        out[base + ((c + 1) << 10)] = q[j].y;
        out[base + ((c + 2) << 10)] = q[j].z;
        out[base + ((c + 3) << 10)] = q[j].w;
    }
#pragma unroll
    for (int o = 16; o > 0; o >>= 1)
        acc += __shfl_down_sync(0xffffffffu, acc, o);
    __shared__ float red[8];
    if ((threadIdx.x & 31) == 0) red[threadIdx.x >> 5] = acc;
    __syncthreads();
    if (threadIdx.x == 0) {
        float s = 0.f;
#pragma unroll
        for (int w = 0; w < 8; ++w) s += red[w];
        atomicAdd(&g_losssum, s);
    }
}

// ---------------------------------------------------------------------------
// Finalize: perplexity + loss scalars
// ---------------------------------------------------------------------------
__global__ void finalize_kernel(const int* __restrict__ flg,
                                float* __restrict__ out, int write_scalars) {
    const int k = threadIdx.x;
    float e = (float)g_hist[k] * (1.f / (float)NTOK);
    float t = e * logf(e + 1e-10f);
#pragma unroll
    for (int o = 16; o > 0; o >>= 1)
        t += __shfl_down_sync(0xffffffffu, t, o);
    __shared__ float red[32];
    if ((k & 31) == 0) red[k >> 5] = t;
    __syncthreads();
    if (k < 32) {
        float v = red[k];
#pragma unroll
        for (int o = 16; o > 0; o >>= 1)
            v += __shfl_down_sync(0xffffffffu, v, o);
        if (k == 0 && write_scalars) {
            int fbits = *flg;
            float loss = (fbits != 0)
                       ? 1.25f * g_losssum * (1.f / (float)ZQ_ELEMS)
                       : 0.f;
            out[ZQ_ELEMS]     = loss;
            out[ZQ_ELEMS + 1] = expf(-v);
        }
    }
}

// ---------------------------------------------------------------------------
extern "C" void kernel_launch(void* const* d_in, const int* in_sizes, int n_in,
                              void* d_out, int out_size) {
    const float* z   = (const float*)d_in[0];
    const float* cb  = (const float*)d_in[1];
    const int*   flg = (const int*)d_in[3];
    float* out = (float*)d_out;

    prep_kernel<<<8, 128>>>(cb);
    argmin_mma_kernel<<<NTOK / 128, 256>>>(z);
    rescue_kernel<<<296, 256>>>(z);
    epilogue_kernel<<<NTOK / 64, 256>>>(z, cb, out);
    finalize_kernel<<<1, 1024>>>(flg, out, out_size >= ZQ_ELEMS + 2 ? 1 : 0);
}

// round 12
// speedup vs baseline: 2.8364x; 1.0763x over previous
#include <cuda_runtime.h>
#include <cuda_fp16.h>
#include <math.h>
#include <stdint.h>

// Problem constants
#define NB     64
#define DIM    64
#define HW     1024
#define NTOK   65536         // NB*HW
#define KCODES 1024
#define ZQ_ELEMS 4194304     // NB*DIM*HW
#define CHUNK  64            // codes per smem chunk (argmin)
#define NCHUNKS (KCODES / CHUNK)   // 16
#define EPS    0.065f

// ---------------------------------------------------------------------------
// Device global scratch (no allocation allowed)
// ---------------------------------------------------------------------------
__device__ __align__(16) uint2 g_cbf[NCHUNKS * 8 * 4 * 32];   // fp16 fragments, 128 KB
__device__ __align__(16) float g_cbT[DIM * KCODES];           // transposed fp32, 256 KB
__device__ __align__(16) float g_cnorm[KCODES];
__device__ int   g_idx[NTOK];
__device__ int   g_rescue[NTOK];
__device__ int   g_rescue_cnt;
__device__ float g_losssum;
__device__ int   g_hist[KCODES];

// ---------------------------------------------------------------------------
// Helpers
// ---------------------------------------------------------------------------
__device__ __forceinline__ void mma16816_f16(float* c, const uint32_t* a,
                                             uint32_t b0, uint32_t b1) {
    asm volatile(
        "mma.sync.aligned.m16n8k16.row.col.f32.f16.f16.f32 "
        "{%0,%1,%2,%3}, {%4,%5,%6,%7}, {%8,%9}, {%0,%1,%2,%3};"
        : "+f"(c[0]), "+f"(c[1]), "+f"(c[2]), "+f"(c[3])
        : "r"(a[0]), "r"(a[1]), "r"(a[2]), "r"(a[3]), "r"(b0), "r"(b1));
}
__device__ __forceinline__ uint32_t pack_h2(float v0, float v1) {
    __half2 h = __floats2half2_rn(v0, v1);
    return *(uint32_t*)&h;
}
__device__ __forceinline__ uint32_t smem_u32(const void* p) {
    uint32_t a;
    asm("{ .reg .u64 t; cvta.to.shared.u64 t, %1; cvt.u32.u64 %0, t; }"
        : "=r"(a) : "l"(p));
    return a;
}
__device__ __forceinline__ void cp16(uint32_t dst, const void* src) {
    asm volatile("cp.async.cg.shared.global [%0], [%1], 16;"
                 :: "r"(dst), "l"(src));
}
#define CP_COMMIT() asm volatile("cp.async.commit_group;" ::: "memory")
#define CP_WAIT0()  asm volatile("cp.async.wait_group 0;" ::: "memory")

// top-2 tracker
__device__ __forceinline__ void upd(float s, int code, float& best, float& sec, int& idx) {
    if (s < best) { sec = best; best = s; idx = code; }
    else if (s < sec) { sec = s; }
}

// ---------------------------------------------------------------------------
// Prep: fp16 fragment codebook + transposed fp32 codebook, ||c||^2, counters
// ---------------------------------------------------------------------------
__global__ void prep_kernel(const float* __restrict__ cb) {
    int k = blockIdx.x * blockDim.x + threadIdx.x;
    if (k >= KCODES) return;
    float v[DIM];
    float s = 0.f;
#pragma unroll
    for (int c = 0; c < DIM; ++c) {
        v[c] = cb[k * DIM + c];
        s = fmaf(v[c], v[c], s);
        g_cbT[c * KCODES + k] = v[c];      // coalesced across k per c
    }
    g_cnorm[k] = s;
    g_hist[k]  = 0;
    if (k == 0) { g_losssum = 0.f; g_rescue_cnt = 0; }

    const int chunk = k >> 6;
    const int n8    = (k & 63) >> 3;
    const int g     = k & 7;
#pragma unroll
    for (int ks = 0; ks < 4; ++ks) {
#pragma unroll
        for (int t4 = 0; t4 < 4; ++t4) {
            int d0 = ks * 16 + t4 * 2;
            int idx = ((chunk * 8 + n8) * 4 + ks) * 32 + g * 4 + t4;
            g_cbf[idx] = make_uint2(pack_h2(v[d0],     v[d0 + 1]),
                                    pack_h2(v[d0 + 8], v[d0 + 9]));
        }
    }
}

// ---------------------------------------------------------------------------
// fp16 HMMA argmin: 8 warps x 16 tokens; 1-term fp16 mma.sync (fp32 accum).
// NEW: computes ||z||^2 per token; for unflagged tokens does hist atomic and
// accumulates loss contribution (||z||^2 + approx best score) here. Flagged
// tokens are deferred entirely to the exact rescue.
// ---------------------------------------------------------------------------
#define SMCN_F   0
#define SMBUF(b) (4096 + (b) * 8192)
#define SM_BYTES (4096 + 2 * 8192)

__global__ void __launch_bounds__(256) argmin_mma_kernel(const float* __restrict__ z) {
    __shared__ __align__(16) char smem[SM_BYTES];
    const uint32_t smb = smem_u32(smem);
    const int tid  = threadIdx.x;
    const int wid  = tid >> 5;
    const int lane = tid & 31;
    const int g    = lane >> 2;
    const int t4   = lane & 3;

    {
        float4* dst = (float4*)(smem + SMCN_F);
        const float4* src = (const float4*)g_cnorm;
        dst[tid] = src[tid];
    }

    const int wbase = blockIdx.x * 128 + wid * 16;
    const int b     = wbase >> 10;
    const int hw0   = (wbase & (HW - 1)) + g;
    const float* zb = z + b * (DIM * HW);
    uint32_t Ah[16];
    float n0 = 0.f, n1 = 0.f;        // partial ||z||^2 for tokens g, g+8
#pragma unroll
    for (int ks = 0; ks < 4; ++ks) {
        int c0 = ks * 16 + t4 * 2;
        float a0 = zb[(c0)     * HW + hw0],     a1 = zb[(c0 + 1) * HW + hw0];
        float b0 = zb[(c0)     * HW + hw0 + 8], b1 = zb[(c0 + 1) * HW + hw0 + 8];
        float a2 = zb[(c0 + 8) * HW + hw0],     a3 = zb[(c0 + 9) * HW + hw0];
        float b2 = zb[(c0 + 8) * HW + hw0 + 8], b3 = zb[(c0 + 9) * HW + hw0 + 8];
        n0 = fmaf(a0, a0, n0); n0 = fmaf(a1, a1, n0);
        n0 = fmaf(a2, a2, n0); n0 = fmaf(a3, a3, n0);
        n1 = fmaf(b0, b0, n1); n1 = fmaf(b1, b1, n1);
        n1 = fmaf(b2, b2, n1); n1 = fmaf(b3, b3, n1);
        Ah[ks * 4 + 0] = pack_h2(a0, a1);
        Ah[ks * 4 + 1] = pack_h2(b0, b1);
        Ah[ks * 4 + 2] = pack_h2(a2, a3);
        Ah[ks * 4 + 3] = pack_h2(b2, b3);
    }

    {
        const char* src = (const char*)g_cbf;
        uint32_t d = smb + SMBUF(0);
#pragma unroll
        for (int i = 0; i < 2; ++i)
            cp16(d + tid * 16 + i * 4096, src + tid * 16 + i * 4096);
        CP_COMMIT();
    }

    float best0 = 3.4e38f, sec0 = 3.4e38f; int idx0 = 0;
    float best1 = 3.4e38f, sec1 = 3.4e38f; int idx1 = 0;

    for (int t = 0; t < NCHUNKS; ++t) {
        const int buf = t & 1;
        CP_WAIT0();
        __syncthreads();

        if (t + 1 < NCHUNKS) {
            const char* src = (const char*)g_cbf + (t + 1) * 8192;
            uint32_t d = smb + SMBUF(1 - buf);
#pragma unroll
            for (int i = 0; i < 2; ++i)
                cp16(d + tid * 16 + i * 4096, src + tid * 16 + i * 4096);
            CP_COMMIT();
        }

        const uint2* bq = (const uint2*)(smem + SMBUF(buf));
        const float* cn = (const float*)(smem + SMCN_F);

#pragma unroll
        for (int n8 = 0; n8 < 8; ++n8) {
            uint2 Bf[4];
#pragma unroll
            for (int ks = 0; ks < 4; ++ks)
                Bf[ks] = bq[(n8 * 4 + ks) * 32 + lane];
            float ae[4] = {0.f, 0.f, 0.f, 0.f};
            float ao[4] = {0.f, 0.f, 0.f, 0.f};
            mma16816_f16(ae, &Ah[0],  Bf[0].x, Bf[0].y);
            mma16816_f16(ao, &Ah[4],  Bf[1].x, Bf[1].y);
            mma16816_f16(ae, &Ah[8],  Bf[2].x, Bf[2].y);
            mma16816_f16(ao, &Ah[12], Bf[3].x, Bf[3].y);

            const int code = t * CHUNK + n8 * 8 + t4 * 2;
            float2 cnv = *(const float2*)(cn + code);
            float s;
            s = fmaf(-2.f, ae[0] + ao[0], cnv.x); upd(s, code,     best0, sec0, idx0);
            s = fmaf(-2.f, ae[1] + ao[1], cnv.y); upd(s, code + 1, best0, sec0, idx0);
            s = fmaf(-2.f, ae[2] + ao[2], cnv.x); upd(s, code,     best1, sec1, idx1);
            s = fmaf(-2.f, ae[3] + ao[3], cnv.y); upd(s, code + 1, best1, sec1, idx1);
        }
        __syncthreads();
    }

    // Reduce top-2 (lex) and norms (sum) across the 4 lanes of each quad
#pragma unroll
    for (int off = 1; off <= 2; off <<= 1) {
        float ob, os; int oi;
        ob = __shfl_xor_sync(0xffffffffu, best0, off);
        os = __shfl_xor_sync(0xffffffffu, sec0,  off);
        oi = __shfl_xor_sync(0xffffffffu, idx0,  off);
        if (ob < best0 || (ob == best0 && oi < idx0)) { sec0 = fminf(best0, os); best0 = ob; idx0 = oi; }
        else                                          { sec0 = fminf(ob, sec0); }
        ob = __shfl_xor_sync(0xffffffffu, best1, off);
        os = __shfl_xor_sync(0xffffffffu, sec1,  off);
        oi = __shfl_xor_sync(0xffffffffu, idx1,  off);
        if (ob < best1 || (ob == best1 && oi < idx1)) { sec1 = fminf(best1, os); best1 = ob; idx1 = oi; }
        else                                          { sec1 = fminf(ob, sec1); }
        n0 += __shfl_xor_sync(0xffffffffu, n0, off);
        n1 += __shfl_xor_sync(0xffffffffu, n1, off);
    }

    float contrib = 0.f;
    if (t4 == 0) {
        const int tok0 = wbase + g;
        const int tok1 = wbase + g + 8;
        g_idx[tok0] = idx0;
        g_idx[tok1] = idx1;
        if (sec0 - best0 < EPS) {
            int s = atomicAdd(&g_rescue_cnt, 1); g_rescue[s] = tok0;
        } else {
            atomicAdd(&g_hist[idx0], 1);
            contrib += n0 + best0;
        }
        if (sec1 - best1 < EPS) {
            int s = atomicAdd(&g_rescue_cnt, 1); g_rescue[s] = tok1;
        } else {
            atomicAdd(&g_hist[idx1], 1);
            contrib += n1 + best1;
        }
    }
    // warp-sum loss contributions, one atomic per warp
#pragma unroll
    for (int o = 16; o > 0; o >>= 1)
        contrib += __shfl_down_sync(0xffffffffu, contrib, o);
    if (lane == 0) atomicAdd(&g_losssum, contrib);
}

// ---------------------------------------------------------------------------
// Rescue: smem-chunked exact fp32 argmin; also writes hist + exact loss
// contribution for its tokens (excluded in argmin).
// ---------------------------------------------------------------------------
__global__ void __launch_bounds__(256) rescue_kernel(const float* __restrict__ z) {
    __shared__ __align__(16) float smZ[32][64];    // 8 KB
    __shared__ __align__(16) float smC[64][128];   // 32 KB, [c][k within chunk]
    const int cnt  = g_rescue_cnt;
    const int tid  = threadIdx.x;
    const int wid  = tid >> 5;
    const int lane = tid & 31;

    for (int base = blockIdx.x * 32; base < cnt; base += gridDim.x * 32) {
        __syncthreads();   // smZ reuse across base iterations
#pragma unroll
        for (int j = 0; j < 8; ++j) {
            int li = tid * 8 + j;              // 0..2047
            int t  = li >> 6;
            int c  = li & 63;
            int gi = base + t;
            int tok = g_rescue[gi < cnt ? gi : cnt - 1];
            int b = tok >> 10, hw = tok & (HW - 1);
            smZ[t][c] = z[b * (DIM * HW) + c * HW + hw];
        }

        float best[4] = {3.4e38f, 3.4e38f, 3.4e38f, 3.4e38f};
        int   bidx[4] = {0, 0, 0, 0};

        for (int ch = 0; ch < 8; ++ch) {
            __syncthreads();
#pragma unroll
            for (int i = 0; i < 8; ++i) {
                int li = tid + i * 256;
                int r  = li >> 5;
                int cc = li & 31;
                ((float4*)smC)[li] = ((const float4*)g_cbT)[r * 256 + ch * 32 + cc];
            }
            __syncthreads();

#pragma unroll
            for (int t = 0; t < 4; ++t) {
                const float* zt = smZ[wid * 4 + t];
                float a0 = 0.f, a1 = 0.f, a2 = 0.f, a3 = 0.f;
#pragma unroll
                for (int c = 0; c < DIM; ++c) {
                    float zc = zt[c];
                    float4 cv = *((const float4*)&smC[c][lane * 4]);
                    a0 = fmaf(zc, cv.x, a0);
                    a1 = fmaf(zc, cv.y, a1);
                    a2 = fmaf(zc, cv.z, a2);
                    a3 = fmaf(zc, cv.w, a3);
                }
                const int k0 = ch * 128 + lane * 4;
                float4 cn = *((const float4*)&g_cnorm[k0]);
                float s;
                s = fmaf(-2.f, a0, cn.x); if (s < best[t]) { best[t] = s; bidx[t] = k0;     }
                s = fmaf(-2.f, a1, cn.y); if (s < best[t]) { best[t] = s; bidx[t] = k0 + 1; }
                s = fmaf(-2.f, a2, cn.z); if (s < best[t]) { best[t] = s; bidx[t] = k0 + 2; }
                s = fmaf(-2.f, a3, cn.w); if (s < best[t]) { best[t] = s; bidx[t] = k0 + 3; }
            }
        }

#pragma unroll
        for (int t = 0; t < 4; ++t) {
            float b_ = best[t]; int i_ = bidx[t];
#pragma unroll
            for (int o = 16; o > 0; o >>= 1) {
                float ob = __shfl_down_sync(0xffffffffu, b_, o);
                int   oi = __shfl_down_sync(0xffffffffu, i_, o);
                if (ob < b_ || (ob == b_ && oi < i_)) { b_ = ob; i_ = oi; }
            }
            // exact ||z||^2 via lane-parallel partial + reduce
            const float* zt = smZ[wid * 4 + t];
            float nv = zt[lane] * zt[lane] + zt[lane + 32] * zt[lane + 32];
#pragma unroll
            for (int o = 16; o > 0; o >>= 1)
                nv += __shfl_down_sync(0xffffffffu, nv, o);
            if (lane == 0) {
                int gi = base + wid * 4 + t;
                if (gi < cnt) {
                    int tok = g_rescue[gi];
                    g_idx[tok] = i_;
                    atomicAdd(&g_hist[i_], 1);
                    atomicAdd(&g_losssum, nv + b_);
                }
            }
        }
    }
}

// ---------------------------------------------------------------------------
// Epilogue-lite: gather codebook -> NCHW out. Block 0 additionally emits the
// loss + perplexity scalars (hist/losssum are final before this launch).
// ---------------------------------------------------------------------------
__global__ void __launch_bounds__(256) epilogue_kernel(const float* __restrict__ cb,
                                                       float* __restrict__ out,
                                                       const int* __restrict__ flg,
                                                       int write_scalars) {
    const int sub  = threadIdx.x >> 6;           // 0..3 -> channel group
    const int tpos = threadIdx.x & 63;
    const int n    = blockIdx.x * 64 + tpos;
    const int b    = n >> 10;
    const int hw   = n & (HW - 1);
    const int idx  = g_idx[n];
    const float4* cbr = (const float4*)(cb + idx * DIM) + sub * 4;
    const int base = b * (DIM * HW) + hw + (sub << 14);   // sub*16 channels

    float4 q[4];
#pragma unroll
    for (int j = 0; j < 4; ++j) q[j] = __ldg(cbr + j);
#pragma unroll
    for (int j = 0; j < 4; ++j) {
        const int c = j * 4;
        out[base + ((c + 0) << 10)] = q[j].x;
        out[base + ((c + 1) << 10)] = q[j].y;
        out[base + ((c + 2) << 10)] = q[j].z;
        out[base + ((c + 3) << 10)] = q[j].w;
    }

    if (blockIdx.x == 0 && write_scalars) {
        // perplexity + loss scalars, computed by block 0 (256 threads x 4 bins)
        float t = 0.f;
#pragma unroll
        for (int j = 0; j < 4; ++j) {
            int k = threadIdx.x * 4 + j;
            float e = (float)g_hist[k] * (1.f / (float)NTOK);
            t = fmaf(e, logf(e + 1e-10f), t);
        }
#pragma unroll
        for (int o = 16; o > 0; o >>= 1)
            t += __shfl_down_sync(0xffffffffu, t, o);
        __shared__ float red[8];
        if ((threadIdx.x & 31) == 0) red[threadIdx.x >> 5] = t;
        __syncthreads();
        if (threadIdx.x == 0) {
            float v = 0.f;
#pragma unroll
            for (int w = 0; w < 8; ++w) v += red[w];
            int fbits = *flg;
            float loss = (fbits != 0)
                       ? 1.25f * g_losssum * (1.f / (float)ZQ_ELEMS)
                       : 0.f;
            out[ZQ_ELEMS]     = loss;
            out[ZQ_ELEMS + 1] = expf(-v);
        }
    }
}

// ---------------------------------------------------------------------------
extern "C" void kernel_launch(void* const* d_in, const int* in_sizes, int n_in,
                              void* d_out, int out_size) {
    const float* z   = (const float*)d_in[0];
    const float* cb  = (const float*)d_in[1];
    const int*   flg = (const int*)d_in[3];
    float* out = (float*)d_out;

    prep_kernel<<<8, 128>>>(cb);
    argmin_mma_kernel<<<NTOK / 128, 256>>>(z);
    rescue_kernel<<<296, 256>>>(z);
    epilogue_kernel<<<NTOK / 64, 256>>>(cb, out, flg,
                                        out_size >= ZQ_ELEMS + 2 ? 1 : 0);
}